// round 10
// baseline (speedup 1.0000x reference)
#include <cuda_runtime.h>
#include <math.h>
#include <stdint.h>

// ---------------- problem constants ----------------
#define BATCH 2
#define TLEN 1024
#define DMODEL 2048
#define HKN 8
#define HVN 16
#define DKH 128
#define DVH 128
#define KWIN 4
#define KEY_DIM 1024
#define VALUE_DIM 2048
#define CONV_DIM 4096
#define MROWS (BATCH * TLEN)   // 2048

// ---------------- scratch (__device__ globals) --------------------------
__device__ float g_mixed[MROWS * CONV_DIM];
__device__ float g_q[MROWS * KEY_DIM];
__device__ float g_k[MROWS * KEY_DIM];
__device__ float g_v[MROWS * VALUE_DIM];
__device__ float g_z[MROWS * VALUE_DIM];
__device__ float g_beta[MROWS * HVN];
__device__ float g_eg[MROWS * HVN];
__device__ float g_o[MROWS * VALUE_DIM];
__device__ float g_yf[MROWS * VALUE_DIM];

// int8 double-word quantized operands
__device__ __align__(16) char g_h1[MROWS * DMODEL];
__device__ __align__(16) char g_h2[MROWS * DMODEL];
__device__ __align__(16) char g_y1[MROWS * VALUE_DIM];
__device__ __align__(16) char g_y2[MROWS * VALUE_DIM];
__device__ __align__(16) char g_wq1[CONV_DIM * DMODEL];
__device__ __align__(16) char g_wq2[CONV_DIM * DMODEL];
__device__ __align__(16) char g_wz1[VALUE_DIM * DMODEL];
__device__ __align__(16) char g_wz2[VALUE_DIM * DMODEL];
__device__ __align__(16) char g_wo1[DMODEL * VALUE_DIM];
__device__ __align__(16) char g_wo2[DMODEL * VALUE_DIM];
// scales: s = maxabs/127 ; value ≈ s*(X1 + X2/128)
__device__ float g_saH[MROWS];
__device__ float g_saY[MROWS];
__device__ float g_sbQ[CONV_DIM];
__device__ float g_sbZ[VALUE_DIM];
__device__ float g_sbO[DMODEL];

// ---------------- helpers ----------------------------------------------
__device__ __forceinline__ uint32_t smem_u32(const void* p) {
    uint32_t a;
    asm("{ .reg .u64 t; cvta.to.shared.u64 t, %1; cvt.u32.u64 %0, t; }"
        : "=r"(a) : "l"(p));
    return a;
}

#define CP_ASYNC16(sa, ga) \
    asm volatile("cp.async.cg.shared.global [%0], [%1], 16;" \
                 :: "r"(sa), "l"(ga) : "memory")
#define CP_COMMIT() asm volatile("cp.async.commit_group;" ::: "memory")
#define CP_WAIT2()  asm volatile("cp.async.wait_group 2;" ::: "memory")

#define LDSM_X4(r, a) \
    asm volatile("ldmatrix.sync.aligned.m8n8.x4.shared.b16 {%0,%1,%2,%3}, [%4];" \
                 : "=r"((r)[0]), "=r"((r)[1]), "=r"((r)[2]), "=r"((r)[3]) \
                 : "r"(a))

#define IMMA16832(c, a, b) \
    asm volatile("mma.sync.aligned.m16n8k32.row.col.s32.s8.s8.s32 " \
                 "{%0,%1,%2,%3}, {%4,%5,%6,%7}, {%8,%9}, {%0,%1,%2,%3};" \
                 : "+r"((c)[0]), "+r"((c)[1]), "+r"((c)[2]), "+r"((c)[3]) \
                 : "r"((a)[0]), "r"((a)[1]), "r"((a)[2]), "r"((a)[3]), \
                   "r"((b)[0]), "r"((b)[1]))

__device__ __forceinline__ int q_clamp127(int v) {
    return v > 127 ? 127 : (v < -127 ? -127 : v);
}

// ---------------- quantization kernels ----------------------------------
// per-column maxabs of W [2048][Ncols]
__global__ __launch_bounds__(256)
void wmax_kernel(const float* __restrict__ W, int Ncols, int which) {
    float* sb = (which == 0) ? g_sbQ : (which == 1) ? g_sbZ : g_sbO;
    const int col = blockIdx.x * 256 + threadIdx.x;
    float m = 0.f;
    for (int k = 0; k < DMODEL; k++)
        m = fmaxf(m, fabsf(W[(size_t)k * Ncols + col]));
    sb[col] = m * (1.f / 127.f);
}

// transpose + double-word quantize: W [2048][Ncols] -> [Ncols][2048] s8 pair
__global__ __launch_bounds__(256)
void wsplit2_kernel(const float* __restrict__ src, int Ncols, int which) {
    char *d1, *d2;
    const float* sb;
    if (which == 0) { d1 = g_wq1; d2 = g_wq2; sb = g_sbQ; }
    else if (which == 1) { d1 = g_wz1; d2 = g_wz2; sb = g_sbZ; }
    else { d1 = g_wo1; d2 = g_wo2; sb = g_sbO; }

    __shared__ float tile[32][33];
    const int tx = threadIdx.x & 31, ty = threadIdx.x >> 5;
    const int bx = blockIdx.x, by = blockIdx.y;
#pragma unroll
    for (int j = 0; j < 4; j++)
        tile[ty + j * 8][tx] =
            src[(size_t)(by * 32 + ty + j * 8) * Ncols + bx * 32 + tx];
    __syncthreads();
#pragma unroll
    for (int j = 0; j < 4; j++) {
        float v = tile[tx][ty + j * 8];
        const int n = bx * 32 + ty + j * 8;
        float s = sb[n];
        float c1 = (s > 0.f) ? (1.f / s) : 0.f;
        int q1 = q_clamp127(__float2int_rn(v * c1));
        float rr = fmaf(v, c1, -(float)q1);
        int q2 = __float2int_rn(rr * 128.f);
        size_t idx = (size_t)n * 2048 + by * 32 + tx;
        d1[idx] = (char)q1;
        d2[idx] = (char)q2;
    }
}

// per-row quantize of a [2048][2048] fp32 matrix (H or y)
__global__ __launch_bounds__(256)
void quantA_kernel(const float* __restrict__ hsrc, int which) {
    const float* src = (which == 0) ? hsrc : g_yf;
    char* d1 = (which == 0) ? g_h1 : g_y1;
    char* d2 = (which == 0) ? g_h2 : g_y2;
    float* sa = (which == 0) ? g_saH : g_saY;

    const int row = blockIdx.x;
    const int tid = threadIdx.x;
    const float* r = src + (size_t)row * 2048;
    float4 va = ((const float4*)r)[tid * 2];
    float4 vb = ((const float4*)r)[tid * 2 + 1];
    float f[8] = {va.x, va.y, va.z, va.w, vb.x, vb.y, vb.z, vb.w};

    float m = 0.f;
#pragma unroll
    for (int i = 0; i < 8; i++) m = fmaxf(m, fabsf(f[i]));
#pragma unroll
    for (int off = 16; off > 0; off >>= 1)
        m = fmaxf(m, __shfl_xor_sync(0xffffffffu, m, off));

    __shared__ float wm[8];
    __shared__ float s_c1;
    if ((tid & 31) == 0) wm[tid >> 5] = m;
    __syncthreads();
    if (tid == 0) {
        float bm = 0.f;
#pragma unroll
        for (int i = 0; i < 8; i++) bm = fmaxf(bm, wm[i]);
        sa[row] = bm * (1.f / 127.f);
        s_c1 = (bm > 0.f) ? (127.f / bm) : 0.f;
    }
    __syncthreads();
    const float c1 = s_c1;

    uint32_t w1[2] = {0, 0}, w2[2] = {0, 0};
#pragma unroll
    for (int i = 0; i < 8; i++) {
        int q1 = q_clamp127(__float2int_rn(f[i] * c1));
        float rr = fmaf(f[i], c1, -(float)q1);
        int q2 = __float2int_rn(rr * 128.f);
        w1[i >> 2] |= (uint32_t)(q1 & 0xFF) << ((i & 3) * 8);
        w2[i >> 2] |= (uint32_t)(q2 & 0xFF) << ((i & 3) * 8);
    }
    ((uint2*)(d1 + (size_t)row * 2048))[tid] = make_uint2(w1[0], w1[1]);
    ((uint2*)(d2 + (size_t)row * 2048))[tid] = make_uint2(w2[0], w2[1]);
}

// ---------------- int8 double-word GEMM ----------------------------------
// C[M,N] = sum sA[m]*sB[n]*(A1B1 + (A1B2+A2B1)/128), K=2048.
// CTA tile 128x128, K-chunk 64 (2 x k32), 4-stage cp.async, 8 warps 64x32.
#define QMAT 10240                 // 128 rows * 80B stride (64B data)
#define QSTG (4 * QMAT)            // A1,A2,B1,B2
#define QNST 4
#define QSMEM (QNST * QSTG)        // 163840

__global__ __launch_bounds__(256, 1)
void gemm_i8(float* __restrict__ Cext, int N, int mode) {
    extern __shared__ char sm[];
    const uint32_t sbase = smem_u32(sm);
    const int tid = threadIdx.x;
    const int wid = tid >> 5, lane = tid & 31;
    const int bn = blockIdx.x * 128, bm = blockIdx.y * 128;
    const int warp_m = (wid >> 2) * 64, warp_n = (wid & 3) * 32;

    const char *A1p, *A2p, *B1p, *B2p;
    const float *sA, *sB;
    float* C;
    if (mode == 0) {
        A1p = g_h1; A2p = g_h2; B1p = g_wq1; B2p = g_wq2;
        sA = g_saH; sB = g_sbQ; C = g_mixed;
    } else if (mode == 1) {
        A1p = g_h1; A2p = g_h2; B1p = g_wz1; B2p = g_wz2;
        sA = g_saH; sB = g_sbZ; C = g_z;
    } else {
        A1p = g_y1; A2p = g_y2; B1p = g_wo1; B2p = g_wo2;
        sA = g_saY; sB = g_sbO; C = Cext;
    }
    const char* gsrc[4] = {A1p, A2p, B1p, B2p};

    const int lrow = tid >> 1;           // 0..127
    const int lhalf = (tid & 1) * 32;    // byte offset 0/32

    auto issue = [&](int kc, int st) {
        const uint32_t stb = sbase + (uint32_t)st * QSTG;
#pragma unroll
        for (int m = 0; m < 4; m++) {
            const int rb = (m < 2) ? bm : bn;
            const char* g = gsrc[m] + (size_t)(rb + lrow) * 2048 + kc * 64 + lhalf;
            const uint32_t sa = stb + (uint32_t)m * QMAT + lrow * 80 + lhalf;
            CP_ASYNC16(sa, g);
            CP_ASYNC16(sa + 16, g + 16);
        }
    };

    int acc1[4][4][4], acc2[4][4][4];
#pragma unroll
    for (int i = 0; i < 4; i++)
#pragma unroll
        for (int j = 0; j < 4; j++)
#pragma unroll
            for (int r = 0; r < 4; r++) { acc1[i][j][r] = 0; acc2[i][j][r] = 0; }

    issue(0, 0); CP_COMMIT();
    issue(1, 1); CP_COMMIT();
    issue(2, 2); CP_COMMIT();

    const int fr_row = (lane & 7) + ((lane >> 3) & 1) * 8;  // 0..15
    const int fr_kg = (lane >> 4) * 16;                     // 0/16

    for (int kc = 0; kc < 32; kc++) {
        CP_WAIT2();
        __syncthreads();

        const uint32_t stb = sbase + (uint32_t)(kc & 3) * QSTG;
        const uint32_t A1s = stb;
        const uint32_t A2s = stb + QMAT;
        const uint32_t B1s = stb + 2 * QMAT;
        const uint32_t B2s = stb + 3 * QMAT;

#pragma unroll
        for (int k32 = 0; k32 < 2; k32++) {
            const int kb = k32 * 32;
            uint32_t a1[4][4], a2[4][4];
#pragma unroll
            for (int f = 0; f < 4; f++) {
                uint32_t ra = (warp_m + f * 16 + fr_row) * 80 + kb + fr_kg;
                LDSM_X4(a1[f], A1s + ra);
                LDSM_X4(a2[f], A2s + ra);
            }
            uint32_t b1[4][2], b2[4][2];
#pragma unroll
            for (int pp = 0; pp < 2; pp++) {
                uint32_t rb = (warp_n + pp * 16 + fr_row) * 80 + kb + fr_kg;
                uint32_t r[4];
                LDSM_X4(r, B1s + rb);
                b1[2 * pp][0] = r[0]; b1[2 * pp][1] = r[2];
                b1[2 * pp + 1][0] = r[1]; b1[2 * pp + 1][1] = r[3];
                LDSM_X4(r, B2s + rb);
                b2[2 * pp][0] = r[0]; b2[2 * pp][1] = r[2];
                b2[2 * pp + 1][0] = r[1]; b2[2 * pp + 1][1] = r[3];
            }
#pragma unroll
            for (int mi = 0; mi < 4; mi++)
#pragma unroll
                for (int nj = 0; nj < 4; nj++) {
                    IMMA16832(acc1[mi][nj], a1[mi], b1[nj]);
                    IMMA16832(acc2[mi][nj], a1[mi], b2[nj]);
                    IMMA16832(acc2[mi][nj], a2[mi], b1[nj]);
                }
        }

        if (kc + 3 < 32) issue(kc + 3, (kc + 3) & 3);
        CP_COMMIT();
    }

    // epilogue: combine words, apply scales
    const int er = lane >> 2, ec = (lane & 3) * 2;
    const float inv128 = 0.0078125f;
#pragma unroll
    for (int mi = 0; mi < 4; mi++) {
        const int r0 = bm + warp_m + mi * 16 + er;
        const float sa0 = sA[r0], sa1 = sA[r0 + 8];
#pragma unroll
        for (int nj = 0; nj < 4; nj++) {
            const int c0 = bn + warp_n + nj * 8 + ec;
            const float sb0 = sB[c0], sb1 = sB[c0 + 1];
            const int* h = acc1[mi][nj];
            const int* l = acc2[mi][nj];
            float v0 = sa0 * sb0 * fmaf((float)l[0], inv128, (float)h[0]);
            float v1 = sa0 * sb1 * fmaf((float)l[1], inv128, (float)h[1]);
            float v2 = sa1 * sb0 * fmaf((float)l[2], inv128, (float)h[2]);
            float v3 = sa1 * sb1 * fmaf((float)l[3], inv128, (float)h[3]);
            float* cp = C + (size_t)r0 * N + c0;
            *(float2*)cp = make_float2(v0, v1);
            *(float2*)(cp + 8 * (size_t)N) = make_float2(v2, v3);
        }
    }
}

// ---------------- conv + silu + split + l2norm --------------------------
__global__ __launch_bounds__(512)
void conv_kernel(const float* __restrict__ conv_w) {
    const int bt = blockIdx.x;
    const int b = bt >> 10;
    const int t = bt & 1023;
    __shared__ float y[CONV_DIM];
    __shared__ float rsq[16];

    const int tid = threadIdx.x;
    for (int c = tid; c < CONV_DIM; c += 512) {
        float acc = 0.f;
#pragma unroll
        for (int j = 0; j < KWIN; j++) {
            int tt = t - (KWIN - 1) + j;
            if (tt >= 0)
                acc = fmaf(conv_w[c * KWIN + j],
                           g_mixed[(size_t)(b * TLEN + tt) * CONV_DIM + c], acc);
        }
        y[c] = acc / (1.f + expf(-acc));
    }
    __syncthreads();

    const int w = tid >> 5, lane = tid & 31;
    {
        float ss = 0.f;
#pragma unroll
        for (int i = 0; i < 4; i++) {
            float vv = y[w * 128 + lane + 32 * i];
            ss = fmaf(vv, vv, ss);
        }
#pragma unroll
        for (int off = 16; off > 0; off >>= 1)
            ss += __shfl_xor_sync(0xffffffffu, ss, off);
        if (lane == 0) rsq[w] = rsqrtf(ss + 1e-6f);
    }
    __syncthreads();

    const float QSCALE = 0.08838834764831845f;
    for (int c = tid; c < CONV_DIM; c += 512) {
        float val = y[c];
        if (c < KEY_DIM) {
            g_q[(size_t)bt * KEY_DIM + c] = val * rsq[c >> 7] * QSCALE;
        } else if (c < 2 * KEY_DIM) {
            g_k[(size_t)bt * KEY_DIM + (c - KEY_DIM)] = val * rsq[c >> 7];
        } else {
            g_v[(size_t)bt * VALUE_DIM + (c - 2 * KEY_DIM)] = val;
        }
    }
}

// ---------------- gate mini-GEMM ---------------------------------------
__global__ __launch_bounds__(256)
void gate2_kernel(const float* __restrict__ hidden, const float* __restrict__ W_b,
                  const float* __restrict__ W_a, const float* __restrict__ dt_bias,
                  const float* __restrict__ A_log) {
    __shared__ float hs[32][68];
    __shared__ float ws[64][33];
    const int tid = threadIdx.x;
    const int mb = blockIdx.x * 32;
    const int mi = tid >> 3;
    const int c4 = (tid & 7) * 4;
    float a0 = 0.f, a1 = 0.f, a2 = 0.f, a3 = 0.f;

    for (int kc = 0; kc < DMODEL; kc += 64) {
#pragma unroll
        for (int l = 0; l < 2; l++) {
            int t = tid + l * 256;
            int r = t >> 4, cc = (t & 15) * 4;
            *(float4*)&hs[r][cc] =
                *(const float4*)&hidden[(size_t)(mb + r) * DMODEL + kc + cc];
        }
#pragma unroll
        for (int l = 0; l < 8; l++) {
            int t = tid + l * 256;
            int r = t >> 5, cc = t & 31;
            ws[r][cc] = (cc < 16) ? W_b[(size_t)(kc + r) * HVN + cc]
                                  : W_a[(size_t)(kc + r) * HVN + cc - 16];
        }
        __syncthreads();
#pragma unroll
        for (int k = 0; k < 64; k++) {
            float a = hs[mi][k];
            a0 = fmaf(a, ws[k][c4 + 0], a0);
            a1 = fmaf(a, ws[k][c4 + 1], a1);
            a2 = fmaf(a, ws[k][c4 + 2], a2);
            a3 = fmaf(a, ws[k][c4 + 3], a3);
        }
        __syncthreads();
    }
    float accs[4] = {a0, a1, a2, a3};
    const int m = mb + mi;
#pragma unroll
    for (int j = 0; j < 4; j++) {
        int c = c4 + j;
        float s = accs[j];
        if (c < 16) {
            g_beta[(size_t)m * HVN + c] = 1.f / (1.f + expf(-s));
        } else {
            int hh = c - 16;
            float x = s + dt_bias[hh];
            float sp = (x > 20.f) ? x : log1pf(expf(x));
            g_eg[(size_t)m * HVN + hh] = expf(-expf(A_log[hh]) * sp);
        }
    }
}

// ---------------- gated delta-rule scan (256 threads) -------------------
#define NSPLIT 4
__global__ __launch_bounds__(256)
void scan_kernel() {
    const int blk = blockIdx.x;
    const int split = blk & (NSPLIT - 1);
    const int bh = blk >> 2;
    const int b = bh >> 4;
    const int h = bh & 15;
    const int hk = h >> 1;

    const int tid = threadIdx.x;
    const int sub = tid & 7;
    const int colw = tid >> 3;
    const int col = split * 32 + colw;

    __shared__ __align__(16) float ksh[2][160];
    __shared__ __align__(16) float qsh[2][160];
    const int lrow = tid & 127;
    const int lpos = (lrow >> 4) * 20 + (lrow & 15);
    const bool isK = tid < 128;

    float S[16];
#pragma unroll
    for (int i = 0; i < 16; i++) S[i] = 0.f;

    const float* kb = g_k + ((size_t)(b * TLEN) * HKN + hk) * DKH;
    const float* qb = g_q + ((size_t)(b * TLEN) * HKN + hk) * DKH;
    const float* vb = g_v + ((size_t)(b * TLEN) * HVN + h) * DVH + col;
    const float* egb = g_eg + (size_t)(b * TLEN) * HVN + h;
    const float* btb = g_beta + (size_t)(b * TLEN) * HVN + h;
    float* ob = g_o + ((size_t)(b * TLEN) * HVN + h) * DVH + col;

    float ldv = isK ? kb[lrow] : qb[lrow];
    float vr = vb[0];
    float egr = egb[0];
    float btr = btb[0];

    int cur = 0;
    for (int t = 0; t < TLEN; t++) {
        if (isK) ksh[cur][lpos] = ldv; else qsh[cur][lpos] = ldv;
        const float vc = vr, egc = egr, btc = btr;
        __syncthreads();

        if (t + 1 < TLEN) {
            ldv = isK ? kb[(size_t)(t + 1) * KEY_DIM + lrow]
                      : qb[(size_t)(t + 1) * KEY_DIM + lrow];
            vr = vb[(size_t)(t + 1) * VALUE_DIM];
            egr = egb[(size_t)(t + 1) * HVN];
            btr = btb[(size_t)(t + 1) * HVN];
        }

        float kf[16], qf[16];
        const float* kp = &ksh[cur][sub * 20];
        const float* qp = &qsh[cur][sub * 20];
#pragma unroll
        for (int i = 0; i < 16; i += 4) {
            float4 x = *(const float4*)(kp + i);
            kf[i] = x.x; kf[i + 1] = x.y; kf[i + 2] = x.z; kf[i + 3] = x.w;
            float4 yq = *(const float4*)(qp + i);
            qf[i] = yq.x; qf[i + 1] = yq.y; qf[i + 2] = yq.z; qf[i + 3] = yq.w;
        }

        float p0 = 0.f, p1 = 0.f, s0 = 0.f, s1 = 0.f, w0 = 0.f, w1 = 0.f;
#pragma unroll
        for (int i = 0; i < 16; i += 2) {
            p0 = fmaf(kf[i], S[i], p0);
            p1 = fmaf(kf[i + 1], S[i + 1], p1);
            s0 = fmaf(qf[i], S[i], s0);
            s1 = fmaf(qf[i + 1], S[i + 1], s1);
            w0 = fmaf(qf[i], kf[i], w0);
            w1 = fmaf(qf[i + 1], kf[i + 1], w1);
        }
        float p = p0 + p1, qS = s0 + s1, qk = w0 + w1;
#pragma unroll
        for (int off = 1; off <= 4; off <<= 1) {
            p += __shfl_xor_sync(0xffffffffu, p, off);
            qS += __shfl_xor_sync(0xffffffffu, qS, off);
            qk += __shfl_xor_sync(0xffffffffu, qk, off);
        }

        const float va = (vc - egc * p) * btc;
        const float op = fmaf(egc, qS, va * qk);

#pragma unroll
        for (int i = 0; i < 16; i++)
            S[i] = fmaf(S[i], egc, kf[i] * va);

        if (sub == 0) ob[(size_t)t * VALUE_DIM] = op;

        cur ^= 1;
    }
}

// ---------------- gated RMSNorm * silu(z) -> fp32 y ---------------------
__global__ __launch_bounds__(256)
void norm_kernel(const float* __restrict__ nw) {
    const int gw = blockIdx.x * 8 + (threadIdx.x >> 5);
    const int lane = threadIdx.x & 31;
    const int bt = gw >> 4;
    const int h = gw & 15;

    const float* op = g_o + (size_t)gw * DVH;
    const float* zp = g_z + (size_t)bt * VALUE_DIM + h * DVH;

    float vv[4];
    float ss = 0.f;
#pragma unroll
    for (int i = 0; i < 4; i++) {
        vv[i] = op[lane + 32 * i];
        ss = fmaf(vv[i], vv[i], ss);
    }
#pragma unroll
    for (int off = 16; off > 0; off >>= 1)
        ss += __shfl_xor_sync(0xffffffffu, ss, off);

    const float r = rsqrtf(ss * (1.f / 128.f) + 1e-6f);
#pragma unroll
    for (int i = 0; i < 4; i++) {
        int d = lane + 32 * i;
        float zz = zp[d];
        float sil = zz / (1.f + expf(-zz));
        g_yf[(size_t)bt * VALUE_DIM + h * DVH + d] = vv[i] * r * nw[d] * sil;
    }
}

// ---------------- launch ------------------------------------------------
extern "C" void kernel_launch(void* const* d_in, const int* in_sizes, int n_in,
                              void* d_out, int out_size) {
    (void)in_sizes; (void)n_in; (void)out_size;
    const float* hidden  = (const float*)d_in[0];
    const float* W_qkv   = (const float*)d_in[1];
    const float* W_z     = (const float*)d_in[2];
    const float* W_b     = (const float*)d_in[3];
    const float* W_a     = (const float*)d_in[4];
    const float* conv_w  = (const float*)d_in[5];
    const float* dt_bias = (const float*)d_in[6];
    const float* A_log   = (const float*)d_in[7];
    const float* norm_w  = (const float*)d_in[8];
    const float* W_out   = (const float*)d_in[9];
    float* out = (float*)d_out;

    cudaFuncSetAttribute(gemm_i8, cudaFuncAttributeMaxDynamicSharedMemorySize,
                         QSMEM);

    // 0) quantize weights (col scales + transpose) and hidden (row scales)
    wmax_kernel<<<CONV_DIM / 256, 256>>>(W_qkv, CONV_DIM, 0);
    wmax_kernel<<<VALUE_DIM / 256, 256>>>(W_z, VALUE_DIM, 1);
    wmax_kernel<<<DMODEL / 256, 256>>>(W_out, DMODEL, 2);
    wsplit2_kernel<<<dim3(CONV_DIM / 32, DMODEL / 32), 256>>>(W_qkv, CONV_DIM, 0);
    wsplit2_kernel<<<dim3(VALUE_DIM / 32, DMODEL / 32), 256>>>(W_z, VALUE_DIM, 1);
    wsplit2_kernel<<<dim3(DMODEL / 32, VALUE_DIM / 32), 256>>>(W_out, DMODEL, 2);
    quantA_kernel<<<MROWS, 256>>>(hidden, 0);

    // 1) mixed = H @ W_qkv   (int8 double-word)
    gemm_i8<<<dim3(CONV_DIM / 128, MROWS / 128), 256, QSMEM>>>(nullptr, CONV_DIM, 0);
    // 2) conv + silu + split + l2norm
    conv_kernel<<<MROWS, 512>>>(conv_w);
    // 3) z = H @ W_z
    gemm_i8<<<dim3(VALUE_DIM / 128, MROWS / 128), 256, QSMEM>>>(nullptr, VALUE_DIM, 1);
    // 4) beta / exp(g)
    gate2_kernel<<<MROWS / 32, 256>>>(hidden, W_b, W_a, dt_bias, A_log);
    // 5) recurrence
    scan_kernel<<<BATCH * HVN * NSPLIT, 256>>>();
    // 6) gated RMSNorm * silu(z) -> g_yf
    norm_kernel<<<MROWS * HVN / 8, 256>>>(norm_w);
    // 7) quantize y, then out = y @ W_out
    quantA_kernel<<<MROWS, 256>>>(nullptr, 1);
    gemm_i8<<<dim3(DMODEL / 128, MROWS / 128), 256, QSMEM>>>(out, DMODEL, 2);
}

// round 11
// speedup vs baseline: 1.6514x; 1.6514x over previous
#include <cuda_runtime.h>
#include <cuda_fp16.h>
#include <math.h>
#include <stdint.h>

// ---------------- problem constants ----------------
#define BATCH 2
#define TLEN 1024
#define DMODEL 2048
#define HKN 8
#define HVN 16
#define DKH 128
#define DVH 128
#define KWIN 4
#define KEY_DIM 1024
#define VALUE_DIM 2048
#define CONV_DIM 4096
#define MROWS (BATCH * TLEN)   // 2048

// ---------------- scratch (__device__ globals) --------------------------
__device__ float g_mixed[MROWS * CONV_DIM];
__device__ float g_q[MROWS * KEY_DIM];
__device__ float g_k[MROWS * KEY_DIM];
__device__ float g_v[MROWS * VALUE_DIM];
__device__ float g_z[MROWS * VALUE_DIM];
__device__ float g_beta[MROWS * HVN];
__device__ float g_eg[MROWS * HVN];
__device__ float g_o[MROWS * VALUE_DIM];

// fp16 hi/lo splits (A operands)
__device__ __align__(16) __half gh_hi[MROWS * DMODEL];
__device__ __align__(16) __half gh_lo[MROWS * DMODEL];
__device__ __align__(16) __half gy_hi[MROWS * VALUE_DIM];
__device__ __align__(16) __half gy_lo[MROWS * VALUE_DIM];
// transposed weights [N][2048] fp16; lo only for W_qkv (3-term GEMM)
__device__ __align__(16) __half wq_hi[CONV_DIM * DMODEL];
__device__ __align__(16) __half wq_lo[CONV_DIM * DMODEL];
__device__ __align__(16) __half wz_hi[VALUE_DIM * DMODEL];
__device__ __align__(16) __half wo_hi[DMODEL * VALUE_DIM];

// ---------------- helpers ----------------------------------------------
__device__ __forceinline__ uint32_t smem_u32(const void* p) {
    uint32_t a;
    asm("{ .reg .u64 t; cvta.to.shared.u64 t, %1; cvt.u32.u64 %0, t; }"
        : "=r"(a) : "l"(p));
    return a;
}

#define CP_ASYNC16(sa, ga) \
    asm volatile("cp.async.cg.shared.global [%0], [%1], 16;" \
                 :: "r"(sa), "l"(ga) : "memory")
#define CP_COMMIT() asm volatile("cp.async.commit_group;" ::: "memory")
#define CP_WAIT1()  asm volatile("cp.async.wait_group 1;" ::: "memory")

#define LDSM_X4(r, a) \
    asm volatile("ldmatrix.sync.aligned.m8n8.x4.shared.b16 {%0,%1,%2,%3}, [%4];" \
                 : "=r"((r)[0]), "=r"((r)[1]), "=r"((r)[2]), "=r"((r)[3]) \
                 : "r"(a))

#define MMA16816(c, a, b) \
    asm volatile("mma.sync.aligned.m16n8k16.row.col.f32.f16.f16.f32 " \
                 "{%0,%1,%2,%3}, {%4,%5,%6,%7}, {%8,%9}, {%0,%1,%2,%3};" \
                 : "+f"((c)[0]), "+f"((c)[1]), "+f"((c)[2]), "+f"((c)[3]) \
                 : "r"((a)[0]), "r"((a)[1]), "r"((a)[2]), "r"((a)[3]), \
                   "r"((b)[0]), "r"((b)[1]))

// ---------------- split kernels ----------------------------------------
__global__ __launch_bounds__(256)
void hsplit_kernel(const float* __restrict__ src) {
    size_t i = ((size_t)blockIdx.x * 256 + threadIdx.x) * 4;
    float4 v = *(const float4*)&src[i];
    float f[4] = {v.x, v.y, v.z, v.w};
#pragma unroll
    for (int j = 0; j < 4; j++) {
        __half hi = __float2half_rn(f[j]);
        gh_hi[i + j] = hi;
        gh_lo[i + j] = __float2half_rn(f[j] - __half2float(hi));
    }
}

// src [2048][Ncols] fp32 -> dst [Ncols][2048] fp16 (transpose; lo optional)
__global__ __launch_bounds__(256)
void wsplit_kernel(const float* __restrict__ src, int Ncols, int which) {
    __half* dh;
    __half* dl = nullptr;
    if (which == 0) { dh = wq_hi; dl = wq_lo; }
    else if (which == 1) { dh = wz_hi; }
    else { dh = wo_hi; }

    __shared__ float tile[32][33];
    const int tx = threadIdx.x & 31, ty = threadIdx.x >> 5;
    const int bx = blockIdx.x, by = blockIdx.y;
#pragma unroll
    for (int j = 0; j < 4; j++)
        tile[ty + j * 8][tx] =
            src[(size_t)(by * 32 + ty + j * 8) * Ncols + bx * 32 + tx];
    __syncthreads();
#pragma unroll
    for (int j = 0; j < 4; j++) {
        float v = tile[tx][ty + j * 8];
        __half hi = __float2half_rn(v);
        size_t idx = (size_t)(bx * 32 + ty + j * 8) * 2048 + by * 32 + tx;
        dh[idx] = hi;
        if (which == 0)
            dl[idx] = __float2half_rn(v - __half2float(hi));
    }
}

// ---------------- mma.sync fp16 split GEMM, tile 128x256 ----------------
// C[M,N] = A[M,2048] @ Bt[N,2048]^T, fp32 out.
// A always split (hi+lo). three=1: B also split (3 products, ~1e-6 err);
// three=0: B single fp16 (2 products, ~1.4e-4 err).
#define A_BYTES 10240              // 128 rows * 80B
#define B_BYTES 20480              // 256 rows * 80B
#define STG_BYTES (2 * A_BYTES + 2 * B_BYTES)   // 61440
#define NSTAGE 3
#define GEMM_SMEM (NSTAGE * STG_BYTES)          // 184320

__global__ __launch_bounds__(256, 1)
void gemm_h(float* __restrict__ Cext, int N, int mode) {
    extern __shared__ char sm[];
    const uint32_t sbase = smem_u32(sm);
    const int tid = threadIdx.x;
    const int wid = tid >> 5, lane = tid & 31;
    const int bn = blockIdx.x * 256, bm = blockIdx.y * 128;
    const int warp_m = (wid >> 2) * 64, warp_n = (wid & 3) * 64;
    const bool three = (mode == 0);

    const __half *gAh, *gAl, *gBh, *gBl = nullptr;
    float* C;
    if (mode == 0) {
        gAh = gh_hi; gAl = gh_lo; gBh = wq_hi; gBl = wq_lo; C = g_mixed;
    } else if (mode == 1) {
        gAh = gh_hi; gAl = gh_lo; gBh = wz_hi; C = g_z;
    } else {
        gAh = gy_hi; gAl = gy_lo; gBh = wo_hi; C = Cext;
    }

    const int arow = tid >> 1;           // 0..127
    const int aq = (tid & 1) * 2;        // 16B chunk 0/2

    auto issue = [&](int kc, int st) {
        const uint32_t stb = sbase + (uint32_t)st * STG_BYTES;
        {
            const size_t go = (size_t)(bm + arow) * 2048 + kc * 32 + aq * 8;
            const uint32_t sa = stb + arow * 80 + aq * 16;
            CP_ASYNC16(sa, gAh + go);
            CP_ASYNC16(sa + 16, gAh + go + 8);
            CP_ASYNC16(sa + A_BYTES, gAl + go);
            CP_ASYNC16(sa + A_BYTES + 16, gAl + go + 8);
        }
        {
            const size_t go = (size_t)(bn + tid) * 2048 + kc * 32;
            const uint32_t sa = stb + 2 * A_BYTES + tid * 80;
#pragma unroll
            for (int c = 0; c < 4; c++)
                CP_ASYNC16(sa + c * 16, gBh + go + c * 8);
            if (three) {
#pragma unroll
                for (int c = 0; c < 4; c++)
                    CP_ASYNC16(sa + B_BYTES + c * 16, gBl + go + c * 8);
            }
        }
    };

    float acc[4][8][4];
#pragma unroll
    for (int i = 0; i < 4; i++)
#pragma unroll
        for (int j = 0; j < 8; j++)
#pragma unroll
            for (int r = 0; r < 4; r++) acc[i][j][r] = 0.f;

    issue(0, 0); CP_COMMIT();
    issue(1, 1); CP_COMMIT();

    const int a_row = lane & 15;
    const int a_kg = (lane >> 4) * 16;
    const int b_row = (lane & 7) + ((lane >> 3) & 1) * 8;
    const int b_kg = (lane >> 4) * 16;

    for (int kc = 0; kc < 64; kc++) {
        CP_WAIT1();
        __syncthreads();

        const uint32_t stb = sbase + (uint32_t)(kc % NSTAGE) * STG_BYTES;
        const uint32_t As_h = stb;
        const uint32_t As_l = stb + A_BYTES;
        const uint32_t Bs_h = stb + 2 * A_BYTES;
        const uint32_t Bs_l = Bs_h + B_BYTES;

#pragma unroll
        for (int k16 = 0; k16 < 2; k16++) {
            const int kb = k16 * 32;
            uint32_t ah[4][4], al[4][4];
#pragma unroll
            for (int f = 0; f < 4; f++) {
                uint32_t ra = (warp_m + f * 16 + a_row) * 80 + kb + a_kg;
                LDSM_X4(ah[f], As_h + ra);
                LDSM_X4(al[f], As_l + ra);
            }
#pragma unroll
            for (int half = 0; half < 2; half++) {
                uint32_t bh[4][2], bl[4][2];
#pragma unroll
                for (int pp = 0; pp < 2; pp++) {
                    const int p = half * 2 + pp;
                    uint32_t rb = (warp_n + p * 16 + b_row) * 80 + kb + b_kg;
                    uint32_t r[4];
                    LDSM_X4(r, Bs_h + rb);
                    bh[2 * pp][0] = r[0]; bh[2 * pp][1] = r[2];
                    bh[2 * pp + 1][0] = r[1]; bh[2 * pp + 1][1] = r[3];
                    if (three) {
                        LDSM_X4(r, Bs_l + rb);
                        bl[2 * pp][0] = r[0]; bl[2 * pp][1] = r[2];
                        bl[2 * pp + 1][0] = r[1]; bl[2 * pp + 1][1] = r[3];
                    }
                }
#pragma unroll
                for (int mi = 0; mi < 4; mi++)
#pragma unroll
                    for (int nj = 0; nj < 4; nj++) {
                        float* a4 = acc[mi][half * 4 + nj];
                        MMA16816(a4, ah[mi], bh[nj]);
                        MMA16816(a4, al[mi], bh[nj]);
                        if (three) MMA16816(a4, ah[mi], bl[nj]);
                    }
            }
        }

        if (kc + 2 < 64) issue(kc + 2, (kc + 2) % NSTAGE);
        CP_COMMIT();
    }

    const int er = lane >> 2, ec = (lane & 3) * 2;
#pragma unroll
    for (int mi = 0; mi < 4; mi++) {
#pragma unroll
        for (int ni = 0; ni < 8; ni++) {
            float* c0 = C + (size_t)(bm + warp_m + mi * 16 + er) * N +
                        bn + warp_n + ni * 8 + ec;
            *(float2*)c0 = make_float2(acc[mi][ni][0], acc[mi][ni][1]);
            *(float2*)(c0 + 8 * (size_t)N) =
                make_float2(acc[mi][ni][2], acc[mi][ni][3]);
        }
    }
}

// ---------------- conv + silu + split + l2norm --------------------------
__global__ __launch_bounds__(512)
void conv_kernel(const float* __restrict__ conv_w) {
    const int bt = blockIdx.x;
    const int b = bt >> 10;
    const int t = bt & 1023;
    __shared__ float y[CONV_DIM];
    __shared__ float rsq[16];

    const int tid = threadIdx.x;
    for (int c = tid; c < CONV_DIM; c += 512) {
        float acc = 0.f;
#pragma unroll
        for (int j = 0; j < KWIN; j++) {
            int tt = t - (KWIN - 1) + j;
            if (tt >= 0)
                acc = fmaf(conv_w[c * KWIN + j],
                           g_mixed[(size_t)(b * TLEN + tt) * CONV_DIM + c], acc);
        }
        y[c] = acc / (1.f + expf(-acc));
    }
    __syncthreads();

    const int w = tid >> 5, lane = tid & 31;
    {
        float ss = 0.f;
#pragma unroll
        for (int i = 0; i < 4; i++) {
            float vv = y[w * 128 + lane + 32 * i];
            ss = fmaf(vv, vv, ss);
        }
#pragma unroll
        for (int off = 16; off > 0; off >>= 1)
            ss += __shfl_xor_sync(0xffffffffu, ss, off);
        if (lane == 0) rsq[w] = rsqrtf(ss + 1e-6f);
    }
    __syncthreads();

    const float QSCALE = 0.08838834764831845f;
    for (int c = tid; c < CONV_DIM; c += 512) {
        float val = y[c];
        if (c < KEY_DIM) {
            g_q[(size_t)bt * KEY_DIM + c] = val * rsq[c >> 7] * QSCALE;
        } else if (c < 2 * KEY_DIM) {
            g_k[(size_t)bt * KEY_DIM + (c - KEY_DIM)] = val * rsq[c >> 7];
        } else {
            g_v[(size_t)bt * VALUE_DIM + (c - 2 * KEY_DIM)] = val;
        }
    }
}

// ---------------- gate mini-GEMM ---------------------------------------
__global__ __launch_bounds__(256)
void gate2_kernel(const float* __restrict__ hidden, const float* __restrict__ W_b,
                  const float* __restrict__ W_a, const float* __restrict__ dt_bias,
                  const float* __restrict__ A_log) {
    __shared__ float hs[32][68];
    __shared__ float ws[64][33];
    const int tid = threadIdx.x;
    const int mb = blockIdx.x * 32;
    const int mi = tid >> 3;
    const int c4 = (tid & 7) * 4;
    float a0 = 0.f, a1 = 0.f, a2 = 0.f, a3 = 0.f;

    for (int kc = 0; kc < DMODEL; kc += 64) {
#pragma unroll
        for (int l = 0; l < 2; l++) {
            int t = tid + l * 256;
            int r = t >> 4, cc = (t & 15) * 4;
            *(float4*)&hs[r][cc] =
                *(const float4*)&hidden[(size_t)(mb + r) * DMODEL + kc + cc];
        }
#pragma unroll
        for (int l = 0; l < 8; l++) {
            int t = tid + l * 256;
            int r = t >> 5, cc = t & 31;
            ws[r][cc] = (cc < 16) ? W_b[(size_t)(kc + r) * HVN + cc]
                                  : W_a[(size_t)(kc + r) * HVN + cc - 16];
        }
        __syncthreads();
#pragma unroll
        for (int k = 0; k < 64; k++) {
            float a = hs[mi][k];
            a0 = fmaf(a, ws[k][c4 + 0], a0);
            a1 = fmaf(a, ws[k][c4 + 1], a1);
            a2 = fmaf(a, ws[k][c4 + 2], a2);
            a3 = fmaf(a, ws[k][c4 + 3], a3);
        }
        __syncthreads();
    }
    float accs[4] = {a0, a1, a2, a3};
    const int m = mb + mi;
#pragma unroll
    for (int j = 0; j < 4; j++) {
        int c = c4 + j;
        float s = accs[j];
        if (c < 16) {
            g_beta[(size_t)m * HVN + c] = 1.f / (1.f + expf(-s));
        } else {
            int hh = c - 16;
            float x = s + dt_bias[hh];
            float sp = (x > 20.f) ? x : log1pf(expf(x));
            g_eg[(size_t)m * HVN + hh] = expf(-expf(A_log[hh]) * sp);
        }
    }
}

// ---------------- gated delta-rule scan (256 threads) -------------------
#define NSPLIT 4
__global__ __launch_bounds__(256)
void scan_kernel() {
    const int blk = blockIdx.x;
    const int split = blk & (NSPLIT - 1);
    const int bh = blk >> 2;
    const int b = bh >> 4;
    const int h = bh & 15;
    const int hk = h >> 1;

    const int tid = threadIdx.x;
    const int sub = tid & 7;
    const int colw = tid >> 3;
    const int col = split * 32 + colw;

    __shared__ __align__(16) float ksh[2][160];
    __shared__ __align__(16) float qsh[2][160];
    const int lrow = tid & 127;
    const int lpos = (lrow >> 4) * 20 + (lrow & 15);
    const bool isK = tid < 128;

    float S[16];
#pragma unroll
    for (int i = 0; i < 16; i++) S[i] = 0.f;

    const float* kb = g_k + ((size_t)(b * TLEN) * HKN + hk) * DKH;
    const float* qb = g_q + ((size_t)(b * TLEN) * HKN + hk) * DKH;
    const float* vb = g_v + ((size_t)(b * TLEN) * HVN + h) * DVH + col;
    const float* egb = g_eg + (size_t)(b * TLEN) * HVN + h;
    const float* btb = g_beta + (size_t)(b * TLEN) * HVN + h;
    float* ob = g_o + ((size_t)(b * TLEN) * HVN + h) * DVH + col;

    float ldv = isK ? kb[lrow] : qb[lrow];
    float vr = vb[0];
    float egr = egb[0];
    float btr = btb[0];

    int cur = 0;
    for (int t = 0; t < TLEN; t++) {
        if (isK) ksh[cur][lpos] = ldv; else qsh[cur][lpos] = ldv;
        const float vc = vr, egc = egr, btc = btr;
        __syncthreads();

        if (t + 1 < TLEN) {
            ldv = isK ? kb[(size_t)(t + 1) * KEY_DIM + lrow]
                      : qb[(size_t)(t + 1) * KEY_DIM + lrow];
            vr = vb[(size_t)(t + 1) * VALUE_DIM];
            egr = egb[(size_t)(t + 1) * HVN];
            btr = btb[(size_t)(t + 1) * HVN];
        }

        float kf[16], qf[16];
        const float* kp = &ksh[cur][sub * 20];
        const float* qp = &qsh[cur][sub * 20];
#pragma unroll
        for (int i = 0; i < 16; i += 4) {
            float4 x = *(const float4*)(kp + i);
            kf[i] = x.x; kf[i + 1] = x.y; kf[i + 2] = x.z; kf[i + 3] = x.w;
            float4 yq = *(const float4*)(qp + i);
            qf[i] = yq.x; qf[i + 1] = yq.y; qf[i + 2] = yq.z; qf[i + 3] = yq.w;
        }

        float p0 = 0.f, p1 = 0.f, s0 = 0.f, s1 = 0.f, w0 = 0.f, w1 = 0.f;
#pragma unroll
        for (int i = 0; i < 16; i += 2) {
            p0 = fmaf(kf[i], S[i], p0);
            p1 = fmaf(kf[i + 1], S[i + 1], p1);
            s0 = fmaf(qf[i], S[i], s0);
            s1 = fmaf(qf[i + 1], S[i + 1], s1);
            w0 = fmaf(qf[i], kf[i], w0);
            w1 = fmaf(qf[i + 1], kf[i + 1], w1);
        }
        float p = p0 + p1, qS = s0 + s1, qk = w0 + w1;
#pragma unroll
        for (int off = 1; off <= 4; off <<= 1) {
            p += __shfl_xor_sync(0xffffffffu, p, off);
            qS += __shfl_xor_sync(0xffffffffu, qS, off);
            qk += __shfl_xor_sync(0xffffffffu, qk, off);
        }

        const float va = (vc - egc * p) * btc;
        const float op = fmaf(egc, qS, va * qk);

#pragma unroll
        for (int i = 0; i < 16; i++)
            S[i] = fmaf(S[i], egc, kf[i] * va);

        if (sub == 0) ob[(size_t)t * VALUE_DIM] = op;

        cur ^= 1;
    }
}

// ---------------- gated RMSNorm * silu(z) -> fp16 hi/lo splits ----------
__global__ __launch_bounds__(256)
void norm_kernel(const float* __restrict__ nw) {
    const int gw = blockIdx.x * 8 + (threadIdx.x >> 5);
    const int lane = threadIdx.x & 31;
    const int bt = gw >> 4;
    const int h = gw & 15;

    const float* op = g_o + (size_t)gw * DVH;
    const float* zp = g_z + (size_t)bt * VALUE_DIM + h * DVH;

    float vv[4];
    float ss = 0.f;
#pragma unroll
    for (int i = 0; i < 4; i++) {
        vv[i] = op[lane + 32 * i];
        ss = fmaf(vv[i], vv[i], ss);
    }
#pragma unroll
    for (int off = 16; off > 0; off >>= 1)
        ss += __shfl_xor_sync(0xffffffffu, ss, off);

    const float r = rsqrtf(ss * (1.f / 128.f) + 1e-6f);
#pragma unroll
    for (int i = 0; i < 4; i++) {
        int d = lane + 32 * i;
        float zz = zp[d];
        float sil = zz / (1.f + expf(-zz));
        float yv = vv[i] * r * nw[d] * sil;
        size_t idx = (size_t)bt * VALUE_DIM + h * DVH + d;
        __half hi = __float2half_rn(yv);
        gy_hi[idx] = hi;
        gy_lo[idx] = __float2half_rn(yv - __half2float(hi));
    }
}

// ---------------- launch ------------------------------------------------
extern "C" void kernel_launch(void* const* d_in, const int* in_sizes, int n_in,
                              void* d_out, int out_size) {
    (void)in_sizes; (void)n_in; (void)out_size;
    const float* hidden  = (const float*)d_in[0];
    const float* W_qkv   = (const float*)d_in[1];
    const float* W_z     = (const float*)d_in[2];
    const float* W_b     = (const float*)d_in[3];
    const float* W_a     = (const float*)d_in[4];
    const float* conv_w  = (const float*)d_in[5];
    const float* dt_bias = (const float*)d_in[6];
    const float* A_log   = (const float*)d_in[7];
    const float* norm_w  = (const float*)d_in[8];
    const float* W_out   = (const float*)d_in[9];
    float* out = (float*)d_out;

    cudaFuncSetAttribute(gemm_h, cudaFuncAttributeMaxDynamicSharedMemorySize,
                         GEMM_SMEM);

    // 0) weight transpose/convert + hidden split
    wsplit_kernel<<<dim3(CONV_DIM / 32, DMODEL / 32), 256>>>(W_qkv, CONV_DIM, 0);
    wsplit_kernel<<<dim3(VALUE_DIM / 32, DMODEL / 32), 256>>>(W_z, VALUE_DIM, 1);
    wsplit_kernel<<<dim3(DMODEL / 32, VALUE_DIM / 32), 256>>>(W_out, DMODEL, 2);
    hsplit_kernel<<<(MROWS * DMODEL) / 1024, 256>>>(hidden);

    // 1) mixed = H @ W_qkv  (3-term, high precision)
    gemm_h<<<dim3(CONV_DIM / 256, MROWS / 128), 256, GEMM_SMEM>>>(nullptr, CONV_DIM, 0);
    // 2) conv + silu + split + l2norm
    conv_kernel<<<MROWS, 512>>>(conv_w);
    // 3) z = H @ W_z  (2-term)
    gemm_h<<<dim3(VALUE_DIM / 256, MROWS / 128), 256, GEMM_SMEM>>>(nullptr, VALUE_DIM, 1);
    // 4) beta / exp(g)
    gate2_kernel<<<MROWS / 32, 256>>>(hidden, W_b, W_a, dt_bias, A_log);
    // 5) recurrence
    scan_kernel<<<BATCH * HVN * NSPLIT, 256>>>();
    // 6) gated RMSNorm * silu(z) -> y fp16 splits
    norm_kernel<<<MROWS * HVN / 8, 256>>>(norm_w);
    // 7) out = y @ W_out  (2-term)
    gemm_h<<<dim3(DMODEL / 256, MROWS / 128), 256, GEMM_SMEM>>>(out, DMODEL, 2);
}

// round 14
// speedup vs baseline: 2.1087x; 1.2769x over previous
#include <cuda_runtime.h>
#include <cuda_fp16.h>
#include <math.h>
#include <stdint.h>

// ---------------- problem constants ----------------
#define BATCH 2
#define TLEN 1024
#define DMODEL 2048
#define HKN 8
#define HVN 16
#define DKH 128
#define DVH 128
#define KWIN 4
#define KEY_DIM 1024
#define VALUE_DIM 2048
#define CONV_DIM 4096
#define MROWS (BATCH * TLEN)   // 2048

// ---------------- scratch (__device__ globals) --------------------------
__device__ float g_mixed[MROWS * CONV_DIM];
__device__ float g_q[MROWS * KEY_DIM];
__device__ float g_k[MROWS * KEY_DIM];
__device__ float g_v[MROWS * VALUE_DIM];
__device__ float g_z[MROWS * VALUE_DIM];
__device__ float g_beta[MROWS * HVN];
__device__ float g_eg[MROWS * HVN];
__device__ float g_o[MROWS * VALUE_DIM];

// fp16 hi/lo splits (A operands); weights single fp16 (2-term GEMMs)
__device__ __align__(16) __half gh_hi[MROWS * DMODEL];
__device__ __align__(16) __half gh_lo[MROWS * DMODEL];
__device__ __align__(16) __half gy_hi[MROWS * VALUE_DIM];
__device__ __align__(16) __half gy_lo[MROWS * VALUE_DIM];
__device__ __align__(16) __half wq_hi[CONV_DIM * DMODEL];
__device__ __align__(16) __half wz_hi[VALUE_DIM * DMODEL];
__device__ __align__(16) __half wo_hi[DMODEL * VALUE_DIM];

// ---------------- streams / events (created at static-init time) --------
static cudaStream_t g_s2 = nullptr;
static cudaEvent_t g_ev_fork = nullptr, g_ev_hsplit = nullptr;
static cudaEvent_t g_ev_gate = nullptr, g_ev_zdone = nullptr;
namespace {
struct StreamInit {
    StreamInit() {
        cudaStreamCreateWithFlags(&g_s2, cudaStreamNonBlocking);
        cudaEventCreateWithFlags(&g_ev_fork, cudaEventDisableTiming);
        cudaEventCreateWithFlags(&g_ev_hsplit, cudaEventDisableTiming);
        cudaEventCreateWithFlags(&g_ev_gate, cudaEventDisableTiming);
        cudaEventCreateWithFlags(&g_ev_zdone, cudaEventDisableTiming);
    }
};
StreamInit g_stream_init;
}

// ---------------- helpers ----------------------------------------------
__device__ __forceinline__ uint32_t smem_u32(const void* p) {
    uint32_t a;
    asm("{ .reg .u64 t; cvta.to.shared.u64 t, %1; cvt.u32.u64 %0, t; }"
        : "=r"(a) : "l"(p));
    return a;
}

#define CP_ASYNC16(sa, ga) \
    asm volatile("cp.async.cg.shared.global [%0], [%1], 16;" \
                 :: "r"(sa), "l"(ga) : "memory")
#define CP_COMMIT() asm volatile("cp.async.commit_group;" ::: "memory")
#define CP_WAIT1()  asm volatile("cp.async.wait_group 1;" ::: "memory")

#define LDSM_X4(r, a) \
    asm volatile("ldmatrix.sync.aligned.m8n8.x4.shared.b16 {%0,%1,%2,%3}, [%4];" \
                 : "=r"((r)[0]), "=r"((r)[1]), "=r"((r)[2]), "=r"((r)[3]) \
                 : "r"(a))

#define MMA16816(c, a, b) \
    asm volatile("mma.sync.aligned.m16n8k16.row.col.f32.f16.f16.f32 " \
                 "{%0,%1,%2,%3}, {%4,%5,%6,%7}, {%8,%9}, {%0,%1,%2,%3};" \
                 : "+f"((c)[0]), "+f"((c)[1]), "+f"((c)[2]), "+f"((c)[3]) \
                 : "r"((a)[0]), "r"((a)[1]), "r"((a)[2]), "r"((a)[3]), \
                   "r"((b)[0]), "r"((b)[1]))

// ---------------- split kernels ----------------------------------------
__global__ __launch_bounds__(256)
void hsplit_kernel(const float* __restrict__ src) {
    size_t i = ((size_t)blockIdx.x * 256 + threadIdx.x) * 4;
    float4 v = *(const float4*)&src[i];
    float f[4] = {v.x, v.y, v.z, v.w};
#pragma unroll
    for (int j = 0; j < 4; j++) {
        __half hi = __float2half_rn(f[j]);
        gh_hi[i + j] = hi;
        gh_lo[i + j] = __float2half_rn(f[j] - __half2float(hi));
    }
}

// src [2048][Ncols] fp32 -> dst [Ncols][2048] fp16 (transpose)
__global__ __launch_bounds__(256)
void wsplit_kernel(const float* __restrict__ src, int Ncols, int which) {
    __half* dh = (which == 0) ? wq_hi : (which == 1) ? wz_hi : wo_hi;

    __shared__ float tile[32][33];
    const int tx = threadIdx.x & 31, ty = threadIdx.x >> 5;
    const int bx = blockIdx.x, by = blockIdx.y;
#pragma unroll
    for (int j = 0; j < 4; j++)
        tile[ty + j * 8][tx] =
            src[(size_t)(by * 32 + ty + j * 8) * Ncols + bx * 32 + tx];
    __syncthreads();
#pragma unroll
    for (int j = 0; j < 4; j++) {
        float v = tile[tx][ty + j * 8];
        size_t idx = (size_t)(bx * 32 + ty + j * 8) * 2048 + by * 32 + tx;
        dh[idx] = __float2half_rn(v);
    }
}

// ---------------- mma.sync fp16 2-term GEMM, tile 128x256 ---------------
// C = (Ahi + Alo) @ Bt^T, fp32 out. A split fp16 pair, B single fp16.
#define A_BYTES 10240              // 128 rows * 80B
#define B_BYTES 20480              // 256 rows * 80B
#define STG_BYTES (2 * A_BYTES + B_BYTES)   // 40960
#define NSTAGE 3
#define GEMM_SMEM (NSTAGE * STG_BYTES)      // 122880

__global__ __launch_bounds__(256, 1)
void gemm_h(float* __restrict__ Cext, int N, int mode) {
    extern __shared__ char sm[];
    const uint32_t sbase = smem_u32(sm);
    const int tid = threadIdx.x;
    const int wid = tid >> 5, lane = tid & 31;
    const int bn = blockIdx.x * 256, bm = blockIdx.y * 128;
    const int warp_m = (wid >> 2) * 64, warp_n = (wid & 3) * 64;

    const __half *gAh, *gAl, *gBh;
    float* C;
    if (mode == 0) {
        gAh = gh_hi; gAl = gh_lo; gBh = wq_hi; C = g_mixed;
    } else if (mode == 1) {
        gAh = gh_hi; gAl = gh_lo; gBh = wz_hi; C = g_z;
    } else {
        gAh = gy_hi; gAl = gy_lo; gBh = wo_hi; C = Cext;
    }

    const int arow = tid >> 1;           // 0..127
    const int aq = (tid & 1) * 2;        // 16B chunk 0/2

    auto issue = [&](int kc, int st) {
        const uint32_t stb = sbase + (uint32_t)st * STG_BYTES;
        {
            const size_t go = (size_t)(bm + arow) * 2048 + kc * 32 + aq * 8;
            const uint32_t sa = stb + arow * 80 + aq * 16;
            CP_ASYNC16(sa, gAh + go);
            CP_ASYNC16(sa + 16, gAh + go + 8);
            CP_ASYNC16(sa + A_BYTES, gAl + go);
            CP_ASYNC16(sa + A_BYTES + 16, gAl + go + 8);
        }
        {
            const size_t go = (size_t)(bn + tid) * 2048 + kc * 32;
            const uint32_t sa = stb + 2 * A_BYTES + tid * 80;
#pragma unroll
            for (int c = 0; c < 4; c++)
                CP_ASYNC16(sa + c * 16, gBh + go + c * 8);
        }
    };

    float acc[4][8][4];
#pragma unroll
    for (int i = 0; i < 4; i++)
#pragma unroll
        for (int j = 0; j < 8; j++)
#pragma unroll
            for (int r = 0; r < 4; r++) acc[i][j][r] = 0.f;

    issue(0, 0); CP_COMMIT();
    issue(1, 1); CP_COMMIT();

    const int a_row = lane & 15;
    const int a_kg = (lane >> 4) * 16;
    const int b_row = (lane & 7) + ((lane >> 3) & 1) * 8;
    const int b_kg = (lane >> 4) * 16;

    for (int kc = 0; kc < 64; kc++) {
        CP_WAIT1();
        __syncthreads();

        const uint32_t stb = sbase + (uint32_t)(kc % NSTAGE) * STG_BYTES;
        const uint32_t As_h = stb;
        const uint32_t As_l = stb + A_BYTES;
        const uint32_t Bs_h = stb + 2 * A_BYTES;

#pragma unroll
        for (int k16 = 0; k16 < 2; k16++) {
            const int kb = k16 * 32;
            uint32_t ah[4][4], al[4][4];
#pragma unroll
            for (int f = 0; f < 4; f++) {
                uint32_t ra = (warp_m + f * 16 + a_row) * 80 + kb + a_kg;
                LDSM_X4(ah[f], As_h + ra);
                LDSM_X4(al[f], As_l + ra);
            }
#pragma unroll
            for (int half = 0; half < 2; half++) {
                uint32_t bh[4][2];
#pragma unroll
                for (int pp = 0; pp < 2; pp++) {
                    const int p = half * 2 + pp;
                    uint32_t rb = (warp_n + p * 16 + b_row) * 80 + kb + b_kg;
                    uint32_t r[4];
                    LDSM_X4(r, Bs_h + rb);
                    bh[2 * pp][0] = r[0]; bh[2 * pp][1] = r[2];
                    bh[2 * pp + 1][0] = r[1]; bh[2 * pp + 1][1] = r[3];
                }
#pragma unroll
                for (int mi = 0; mi < 4; mi++)
#pragma unroll
                    for (int nj = 0; nj < 4; nj++) {
                        float* a4 = acc[mi][half * 4 + nj];
                        MMA16816(a4, ah[mi], bh[nj]);
                        MMA16816(a4, al[mi], bh[nj]);
                    }
            }
        }

        if (kc + 2 < 64) issue(kc + 2, (kc + 2) % NSTAGE);
        CP_COMMIT();
    }

    const int er = lane >> 2, ec = (lane & 3) * 2;
#pragma unroll
    for (int mi = 0; mi < 4; mi++) {
#pragma unroll
        for (int ni = 0; ni < 8; ni++) {
            float* c0 = C + (size_t)(bm + warp_m + mi * 16 + er) * N +
                        bn + warp_n + ni * 8 + ec;
            *(float2*)c0 = make_float2(acc[mi][ni][0], acc[mi][ni][1]);
            *(float2*)(c0 + 8 * (size_t)N) =
                make_float2(acc[mi][ni][2], acc[mi][ni][3]);
        }
    }
}

// ---------------- conv + silu + split + l2norm --------------------------
__global__ __launch_bounds__(512)
void conv_kernel(const float* __restrict__ conv_w) {
    const int bt = blockIdx.x;
    const int b = bt >> 10;
    const int t = bt & 1023;
    __shared__ float y[CONV_DIM];
    __shared__ float rsq[16];

    const int tid = threadIdx.x;
    for (int c = tid; c < CONV_DIM; c += 512) {
        float acc = 0.f;
#pragma unroll
        for (int j = 0; j < KWIN; j++) {
            int tt = t - (KWIN - 1) + j;
            if (tt >= 0)
                acc = fmaf(conv_w[c * KWIN + j],
                           g_mixed[(size_t)(b * TLEN + tt) * CONV_DIM + c], acc);
        }
        y[c] = acc / (1.f + expf(-acc));
    }
    __syncthreads();

    const int w = tid >> 5, lane = tid & 31;
    {
        float ss = 0.f;
#pragma unroll
        for (int i = 0; i < 4; i++) {
            float vv = y[w * 128 + lane + 32 * i];
            ss = fmaf(vv, vv, ss);
        }
#pragma unroll
        for (int off = 16; off > 0; off >>= 1)
            ss += __shfl_xor_sync(0xffffffffu, ss, off);
        if (lane == 0) rsq[w] = rsqrtf(ss + 1e-6f);
    }
    __syncthreads();

    const float QSCALE = 0.08838834764831845f;
    for (int c = tid; c < CONV_DIM; c += 512) {
        float val = y[c];
        if (c < KEY_DIM) {
            g_q[(size_t)bt * KEY_DIM + c] = val * rsq[c >> 7] * QSCALE;
        } else if (c < 2 * KEY_DIM) {
            g_k[(size_t)bt * KEY_DIM + (c - KEY_DIM)] = val * rsq[c >> 7];
        } else {
            g_v[(size_t)bt * VALUE_DIM + (c - 2 * KEY_DIM)] = val;
        }
    }
}

// ---------------- gate mini-GEMM ---------------------------------------
__global__ __launch_bounds__(256)
void gate2_kernel(const float* __restrict__ hidden, const float* __restrict__ W_b,
                  const float* __restrict__ W_a, const float* __restrict__ dt_bias,
                  const float* __restrict__ A_log) {
    __shared__ float hs[32][68];
    __shared__ float ws[64][33];
    const int tid = threadIdx.x;
    const int mb = blockIdx.x * 32;
    const int mi = tid >> 3;
    const int c4 = (tid & 7) * 4;
    float a0 = 0.f, a1 = 0.f, a2 = 0.f, a3 = 0.f;

    for (int kc = 0; kc < DMODEL; kc += 64) {
#pragma unroll
        for (int l = 0; l < 2; l++) {
            int t = tid + l * 256;
            int r = t >> 4, cc = (t & 15) * 4;
            *(float4*)&hs[r][cc] =
                *(const float4*)&hidden[(size_t)(mb + r) * DMODEL + kc + cc];
        }
#pragma unroll
        for (int l = 0; l < 8; l++) {
            int t = tid + l * 256;
            int r = t >> 5, cc = t & 31;
            ws[r][cc] = (cc < 16) ? W_b[(size_t)(kc + r) * HVN + cc]
                                  : W_a[(size_t)(kc + r) * HVN + cc - 16];
        }
        __syncthreads();
#pragma unroll
        for (int k = 0; k < 64; k++) {
            float a = hs[mi][k];
            a0 = fmaf(a, ws[k][c4 + 0], a0);
            a1 = fmaf(a, ws[k][c4 + 1], a1);
            a2 = fmaf(a, ws[k][c4 + 2], a2);
            a3 = fmaf(a, ws[k][c4 + 3], a3);
        }
        __syncthreads();
    }
    float accs[4] = {a0, a1, a2, a3};
    const int m = mb + mi;
#pragma unroll
    for (int j = 0; j < 4; j++) {
        int c = c4 + j;
        float s = accs[j];
        if (c < 16) {
            g_beta[(size_t)m * HVN + c] = 1.f / (1.f + expf(-s));
        } else {
            int hh = c - 16;
            float x = s + dt_bias[hh];
            float sp = (x > 20.f) ? x : log1pf(expf(x));
            g_eg[(size_t)m * HVN + hh] = expf(-expf(A_log[hh]) * sp);
        }
    }
}

// ---------------- gated delta-rule scan (256 threads) -------------------
#define NSPLIT 4
__global__ __launch_bounds__(256)
void scan_kernel() {
    const int blk = blockIdx.x;
    const int split = blk & (NSPLIT - 1);
    const int bh = blk >> 2;
    const int b = bh >> 4;
    const int h = bh & 15;
    const int hk = h >> 1;

    const int tid = threadIdx.x;
    const int sub = tid & 7;
    const int colw = tid >> 3;
    const int col = split * 32 + colw;

    __shared__ __align__(16) float ksh[2][160];
    __shared__ __align__(16) float qsh[2][160];
    const int lrow = tid & 127;
    const int lpos = (lrow >> 4) * 20 + (lrow & 15);
    const bool isK = tid < 128;

    float S[16];
#pragma unroll
    for (int i = 0; i < 16; i++) S[i] = 0.f;

    const float* kb = g_k + ((size_t)(b * TLEN) * HKN + hk) * DKH;
    const float* qb = g_q + ((size_t)(b * TLEN) * HKN + hk) * DKH;
    const float* vb = g_v + ((size_t)(b * TLEN) * HVN + h) * DVH + col;
    const float* egb = g_eg + (size_t)(b * TLEN) * HVN + h;
    const float* btb = g_beta + (size_t)(b * TLEN) * HVN + h;
    float* ob = g_o + ((size_t)(b * TLEN) * HVN + h) * DVH + col;

    float ldv = isK ? kb[lrow] : qb[lrow];
    float vr = vb[0];
    float egr = egb[0];
    float btr = btb[0];

    int cur = 0;
    for (int t = 0; t < TLEN; t++) {
        if (isK) ksh[cur][lpos] = ldv; else qsh[cur][lpos] = ldv;
        const float vc = vr, egc = egr, btc = btr;
        __syncthreads();

        if (t + 1 < TLEN) {
            ldv = isK ? kb[(size_t)(t + 1) * KEY_DIM + lrow]
                      : qb[(size_t)(t + 1) * KEY_DIM + lrow];
            vr = vb[(size_t)(t + 1) * VALUE_DIM];
            egr = egb[(size_t)(t + 1) * HVN];
            btr = btb[(size_t)(t + 1) * HVN];
        }

        float kf[16], qf[16];
        const float* kp = &ksh[cur][sub * 20];
        const float* qp = &qsh[cur][sub * 20];
#pragma unroll
        for (int i = 0; i < 16; i += 4) {
            float4 x = *(const float4*)(kp + i);
            kf[i] = x.x; kf[i + 1] = x.y; kf[i + 2] = x.z; kf[i + 3] = x.w;
            float4 yq = *(const float4*)(qp + i);
            qf[i] = yq.x; qf[i + 1] = yq.y; qf[i + 2] = yq.z; qf[i + 3] = yq.w;
        }

        float p0 = 0.f, p1 = 0.f, s0 = 0.f, s1 = 0.f, w0 = 0.f, w1 = 0.f;
#pragma unroll
        for (int i = 0; i < 16; i += 2) {
            p0 = fmaf(kf[i], S[i], p0);
            p1 = fmaf(kf[i + 1], S[i + 1], p1);
            s0 = fmaf(qf[i], S[i], s0);
            s1 = fmaf(qf[i + 1], S[i + 1], s1);
            w0 = fmaf(qf[i], kf[i], w0);
            w1 = fmaf(qf[i + 1], kf[i + 1], w1);
        }
        float p = p0 + p1, qS = s0 + s1, qk = w0 + w1;
#pragma unroll
        for (int off = 1; off <= 4; off <<= 1) {
            p += __shfl_xor_sync(0xffffffffu, p, off);
            qS += __shfl_xor_sync(0xffffffffu, qS, off);
            qk += __shfl_xor_sync(0xffffffffu, qk, off);
        }

        const float va = (vc - egc * p) * btc;
        const float op = fmaf(egc, qS, va * qk);

#pragma unroll
        for (int i = 0; i < 16; i++)
            S[i] = fmaf(S[i], egc, kf[i] * va);

        if (sub == 0) ob[(size_t)t * VALUE_DIM] = op;

        cur ^= 1;
    }
}

// ---------------- gated RMSNorm * silu(z) -> fp16 hi/lo splits ----------
__global__ __launch_bounds__(256)
void norm_kernel(const float* __restrict__ nw) {
    const int gw = blockIdx.x * 8 + (threadIdx.x >> 5);
    const int lane = threadIdx.x & 31;
    const int bt = gw >> 4;
    const int h = gw & 15;

    const float* op = g_o + (size_t)gw * DVH;
    const float* zp = g_z + (size_t)bt * VALUE_DIM + h * DVH;

    float vv[4];
    float ss = 0.f;
#pragma unroll
    for (int i = 0; i < 4; i++) {
        vv[i] = op[lane + 32 * i];
        ss = fmaf(vv[i], vv[i], ss);
    }
#pragma unroll
    for (int off = 16; off > 0; off >>= 1)
        ss += __shfl_xor_sync(0xffffffffu, ss, off);

    const float r = rsqrtf(ss * (1.f / 128.f) + 1e-6f);
#pragma unroll
    for (int i = 0; i < 4; i++) {
        int d = lane + 32 * i;
        float zz = zp[d];
        float sil = zz / (1.f + expf(-zz));
        float yv = vv[i] * r * nw[d] * sil;
        size_t idx = (size_t)bt * VALUE_DIM + h * DVH + d;
        __half hi = __float2half_rn(yv);
        gy_hi[idx] = hi;
        gy_lo[idx] = __float2half_rn(yv - __half2float(hi));
    }
}

// ---------------- launch ------------------------------------------------
extern "C" void kernel_launch(void* const* d_in, const int* in_sizes, int n_in,
                              void* d_out, int out_size) {
    (void)in_sizes; (void)n_in; (void)out_size;
    const float* hidden  = (const float*)d_in[0];
    const float* W_qkv   = (const float*)d_in[1];
    const float* W_z     = (const float*)d_in[2];
    const float* W_b     = (const float*)d_in[3];
    const float* W_a     = (const float*)d_in[4];
    const float* conv_w  = (const float*)d_in[5];
    const float* dt_bias = (const float*)d_in[6];
    const float* A_log   = (const float*)d_in[7];
    const float* norm_w  = (const float*)d_in[8];
    const float* W_out   = (const float*)d_in[9];
    float* out = (float*)d_out;

    cudaFuncSetAttribute(gemm_h, cudaFuncAttributeMaxDynamicSharedMemorySize,
                         GEMM_SMEM);
    // fallback (should already exist from static init — happens during the
    // uncaptured correctness call at worst)
    if (!g_s2) {
        cudaStreamCreateWithFlags(&g_s2, cudaStreamNonBlocking);
        cudaEventCreateWithFlags(&g_ev_fork, cudaEventDisableTiming);
        cudaEventCreateWithFlags(&g_ev_hsplit, cudaEventDisableTiming);
        cudaEventCreateWithFlags(&g_ev_gate, cudaEventDisableTiming);
        cudaEventCreateWithFlags(&g_ev_zdone, cudaEventDisableTiming);
    }

    // ---- fork: s2 handles W_z/W_out transposes, gates, and the z-GEMM ----
    cudaEventRecord(g_ev_fork, 0);
    cudaStreamWaitEvent(g_s2, g_ev_fork, 0);
    wsplit_kernel<<<dim3(VALUE_DIM / 32, DMODEL / 32), 256, 0, g_s2>>>(W_z, VALUE_DIM, 1);
    wsplit_kernel<<<dim3(DMODEL / 32, VALUE_DIM / 32), 256, 0, g_s2>>>(W_out, DMODEL, 2);
    gate2_kernel<<<MROWS / 32, 256, 0, g_s2>>>(hidden, W_b, W_a, dt_bias, A_log);
    cudaEventRecord(g_ev_gate, g_s2);

    // ---- s0: qkv path ----
    wsplit_kernel<<<dim3(CONV_DIM / 32, DMODEL / 32), 256>>>(W_qkv, CONV_DIM, 0);
    hsplit_kernel<<<(MROWS * DMODEL) / 1024, 256>>>(hidden);
    cudaEventRecord(g_ev_hsplit, 0);

    // s2: z = H @ W_z (2-term) — overlaps with G1/conv/scan on s0
    cudaStreamWaitEvent(g_s2, g_ev_hsplit, 0);
    gemm_h<<<dim3(VALUE_DIM / 256, MROWS / 128), 256, GEMM_SMEM, g_s2>>>(nullptr, VALUE_DIM, 1);
    cudaEventRecord(g_ev_zdone, g_s2);

    // s0: mixed = H @ W_qkv (2-term) -> conv -> scan
    gemm_h<<<dim3(CONV_DIM / 256, MROWS / 128), 256, GEMM_SMEM>>>(nullptr, CONV_DIM, 0);
    conv_kernel<<<MROWS, 512>>>(conv_w);
    cudaStreamWaitEvent(0, g_ev_gate, 0);
    scan_kernel<<<BATCH * HVN * NSPLIT, 256>>>();

    // join: norm needs z (s2) + o (s0)
    cudaStreamWaitEvent(0, g_ev_zdone, 0);
    norm_kernel<<<MROWS * HVN / 8, 256>>>(norm_w);
    // out = y @ W_out (2-term)
    gemm_h<<<dim3(DMODEL / 256, MROWS / 128), 256, GEMM_SMEM>>>(out, DMODEL, 2);
}